// round 1
// baseline (speedup 1.0000x reference)
#include <cuda_runtime.h>
#include <math.h>

#define FULL 0xffffffffu

// Per-block fused-gate coefficients: {cos_sigma, sin_sigma, ar, ai, br, bi, 0, 0}
// c=0: u0 = cs*t0 - ss*t1 ; u1 = ss*t0 + cs*t1
// c=1: u0 = -b*t0 + a*t1  ; u1 = a*t0 + b*t1   (a,b complex; phase e^{i th0} folded in)
__device__ float g_coef[21 * 8];

__global__ void setup_coef(const float* __restrict__ conv,
                           const float* __restrict__ pool) {
    int t = threadIdx.x;
    if (t >= 21) return;
    float t0, t1, t2;
    if (t < 14) {
        int l = t / 7, i = t % 7;
        const float* p = conv + (l * 7 + i) * 3;
        t0 = p[0]; t1 = p[1]; t2 = p[2];
    } else if (t < 18) { t0 = pool[0]; t1 = pool[1]; t2 = pool[2]; }
    else if (t < 20)   { t0 = pool[3]; t1 = pool[4]; t2 = pool[5]; }
    else               { t0 = pool[6]; t1 = pool[7]; t2 = pool[8]; }

    float sg = 0.5f * (t1 + t2);
    float dl = 0.5f * (t2 - t1);
    float cs = cosf(sg), ss = sinf(sg);
    float cd = cosf(dl), sd = sinf(dl);
    float cp = cosf(t0), sp = sinf(t0);
    float* o = g_coef + t * 8;
    o[0] = cs; o[1] = ss;
    o[2] = cp * cd; o[3] = sp * cd;   // a = e^{i th0} * cos(delta)
    o[4] = cp * sd; o[5] = sp * sd;   // b = e^{i th0} * sin(delta)
    o[6] = 0.f; o[7] = 0.f;
}

// CB, TB: control / target index-bit positions (bit b = qubit wire 7-b).
// Register slot r holds index bits {7,6,5}; lane bits are index bits {4..0}.
template<int CB, int TB>
__device__ __forceinline__ void apply_block(float (&re)[8], float (&im)[8],
                                            const float* cf, unsigned lane) {
    float cs = cf[0], ss = cf[1];
    float ar = cf[2], ai = cf[3], br = cf[4], bi = cf[5];

    if constexpr (TB >= 5) {
        // In-register target: pairs over slot bit (TB-5). Control is always a slot bit here.
        static_assert(CB >= 5, "in-lane target gates have in-register control");
        constexpr int tm = 1 << (TB - 5);
#pragma unroll
        for (int r0 = 0; r0 < 8; r0++) {
            if (r0 & tm) continue;
            const int r1 = r0 | tm;
            float x0r = re[r0], x0i = im[r0], x1r = re[r1], x1i = im[r1];
            if (((r0 >> (CB - 5)) & 1) == 0) {
                re[r0] = cs * x0r - ss * x1r;  im[r0] = cs * x0i - ss * x1i;
                re[r1] = ss * x0r + cs * x1r;  im[r1] = ss * x0i + cs * x1i;
            } else {
                re[r0] = -br * x0r + bi * x0i + ar * x1r - ai * x1i;
                im[r0] = -br * x0i - bi * x0r + ar * x1i + ai * x1r;
                re[r1] =  ar * x0r - ai * x0i + br * x1r - bi * x1i;
                im[r1] =  ar * x0i + ai * x0r + br * x1i + bi * x1r;
            }
        }
    } else {
        // Cross-lane target: partner amplitude via shfl_xor(1<<TB).
        const bool side = (lane >> TB) & 1;   // 0: this lane holds t0; 1: holds t1
        if constexpr (CB >= 5) {
            // compile-time control per slot
            float Bs = side ? ss : -ss;        // c=0: u = cs*self + (+-ss)*partner
            float Ar = side ? br : -br;        // c=1: A = +-b, B = a
            float Ai = side ? bi : -bi;
#pragma unroll
            for (int r = 0; r < 8; r++) {
                float pr = __shfl_xor_sync(FULL, re[r], 1 << TB);
                float pi = __shfl_xor_sync(FULL, im[r], 1 << TB);
                if (((r >> (CB - 5)) & 1) == 0) {
                    re[r] = cs * re[r] + Bs * pr;
                    im[r] = cs * im[r] + Bs * pi;
                } else {
                    float xr = re[r], xi = im[r];
                    re[r] = Ar * xr - Ai * xi + ar * pr - ai * pi;
                    im[r] = Ar * xi + Ai * xr + ar * pi + ai * pr;
                }
            }
        } else {
            // lane-bit control (uniform across this lane's 8 slots)
            const bool c = (lane >> CB) & 1;
            float Ar, Ai, Br, Bi;
            if (c) { Ar = side ? br : -br; Ai = side ? bi : -bi; Br = ar; Bi = ai; }
            else   { Ar = cs; Ai = 0.f;    Br = side ? ss : -ss; Bi = 0.f; }
#pragma unroll
            for (int r = 0; r < 8; r++) {
                float pr = __shfl_xor_sync(FULL, re[r], 1 << TB);
                float pi = __shfl_xor_sync(FULL, im[r], 1 << TB);
                float xr = re[r], xi = im[r];
                re[r] = Ar * xr - Ai * xi + Br * pr - Bi * pi;
                im[r] = Ar * xi + Ai * xr + Br * pi + Bi * pr;
            }
        }
    }
}

__global__ void __launch_bounds__(256)
qsim_kernel(const float* __restrict__ x, float* __restrict__ out, int nb) {
    __shared__ float scf[21 * 8];
    for (int t = threadIdx.x; t < 21 * 8; t += blockDim.x) scf[t] = g_coef[t];
    __syncthreads();

    const int warp = threadIdx.x >> 5;
    const unsigned lane = threadIdx.x & 31;
    const int b = blockIdx.x * (blockDim.x >> 5) + warp;
    if (b >= nb) return;

    // ---- initial product state:  amp[i] = prod_q (bit(7-q,i) ? sin(x_q/2) : cos(x_q/2))
    float myx = x[b * 8 + (lane & 7)];
    float sh_, ch_;
    sincosf(0.5f * myx, &sh_, &ch_);
    float cw[8], sw[8];
#pragma unroll
    for (int w = 0; w < 8; w++) {
        cw[w] = __shfl_sync(FULL, ch_, w);
        sw[w] = __shfl_sync(FULL, sh_, w);
    }
    // lane bits k=0..4 are index bits k -> wires 7-k
    float pref = 1.f;
#pragma unroll
    for (int k = 0; k < 5; k++) {
        float f = ((lane >> k) & 1) ? sw[7 - k] : cw[7 - k];
        pref *= f;
    }
    // slot bits: r = b7*4 + b6*2 + b5 -> wires 0,1,2
    float q01[4];
    q01[0] = cw[0] * cw[1]; q01[1] = cw[0] * sw[1];
    q01[2] = sw[0] * cw[1]; q01[3] = sw[0] * sw[1];
    float re[8], im[8];
#pragma unroll
    for (int r = 0; r < 8; r++) {
        float t = q01[r >> 1] * ((r & 1) ? sw[2] : cw[2]);
        re[r] = t * pref;
        im[r] = 0.f;
    }

    // ---- 21 fused blocks. conv i: (CB,TB) = (7-i, 6-i)
    apply_block<7, 6>(re, im, scf + 0 * 8, lane);
    apply_block<6, 5>(re, im, scf + 1 * 8, lane);
    apply_block<5, 4>(re, im, scf + 2 * 8, lane);
    apply_block<4, 3>(re, im, scf + 3 * 8, lane);
    apply_block<3, 2>(re, im, scf + 4 * 8, lane);
    apply_block<2, 1>(re, im, scf + 5 * 8, lane);
    apply_block<1, 0>(re, im, scf + 6 * 8, lane);

    apply_block<7, 6>(re, im, scf + 7 * 8, lane);
    apply_block<6, 5>(re, im, scf + 8 * 8, lane);
    apply_block<5, 4>(re, im, scf + 9 * 8, lane);
    apply_block<4, 3>(re, im, scf + 10 * 8, lane);
    apply_block<3, 2>(re, im, scf + 11 * 8, lane);
    apply_block<2, 1>(re, im, scf + 12 * 8, lane);
    apply_block<1, 0>(re, im, scf + 13 * 8, lane);

    // pool0: (0,4),(1,5),(2,6),(3,7) -> (7,3),(6,2),(5,1),(4,0)
    apply_block<7, 3>(re, im, scf + 14 * 8, lane);
    apply_block<6, 2>(re, im, scf + 15 * 8, lane);
    apply_block<5, 1>(re, im, scf + 16 * 8, lane);
    apply_block<4, 0>(re, im, scf + 17 * 8, lane);
    // pool1: (0,2),(1,3) -> (7,5),(6,4)
    apply_block<7, 5>(re, im, scf + 18 * 8, lane);
    apply_block<6, 4>(re, im, scf + 19 * 8, lane);
    // pool2: (0,1) -> (7,6)
    apply_block<7, 6>(re, im, scf + 20 * 8, lane);

    // ---- readout: <Z_q> = sum_i |amp_i|^2 * (-1)^{bit(7-q,i)}
    float p[8];
#pragma unroll
    for (int r = 0; r < 8; r++) p[r] = re[r] * re[r] + im[r] * im[r];

    float a0 = p[0] + p[1], a1 = p[2] + p[3], a2 = p[4] + p[5], a3 = p[6] + p[7];
    float b01 = a0 + a1, b23 = a2 + a3;
    float S = b01 + b23;
    float v[8];
    v[0] = b01 - b23;                                     // wire0 (bit7 = r&4)
    v[1] = (a0 - a1) + (a2 - a3);                         // wire1 (bit6 = r&2)
    v[2] = (p[0] - p[1]) + (p[2] - p[3]) + (p[4] - p[5]) + (p[6] - p[7]);  // wire2 (bit5)
    v[3] = S; v[4] = S; v[5] = S; v[6] = S; v[7] = S;     // wires 3..7 (lane bits 4..0)

#pragma unroll
    for (int k = 0; k < 5; k++) {
        const int m = 1 << k;
        const int qs = 7 - k;             // output whose sign flips with lane bit k
        const bool hi = (lane >> k) & 1;
#pragma unroll
        for (int j = 0; j < 8; j++) {
            float t = __shfl_xor_sync(FULL, v[j], m);
            if (j == qs) v[j] = hi ? (t - v[j]) : (v[j] - t);
            else         v[j] = v[j] + t;
        }
    }

    if (lane == 0) {
        float4* o = (float4*)(out + (size_t)b * 8);
        o[0] = make_float4(v[0], v[1], v[2], v[3]);
        o[1] = make_float4(v[4], v[5], v[6], v[7]);
    }
}

extern "C" void kernel_launch(void* const* d_in, const int* in_sizes, int n_in,
                              void* d_out, int out_size) {
    const float* x    = (const float*)d_in[0];
    const float* conv = (const float*)d_in[1];
    const float* pool = (const float*)d_in[2];
    float* out = (float*)d_out;

    int nb = in_sizes[0] / 8;   // 65536 batch elements

    setup_coef<<<1, 32>>>(conv, pool);

    const int WARPS_PER_BLOCK = 8;
    int blocks = (nb + WARPS_PER_BLOCK - 1) / WARPS_PER_BLOCK;
    qsim_kernel<<<blocks, WARPS_PER_BLOCK * 32>>>(x, out, nb);
}